// round 5
// baseline (speedup 1.0000x reference)
#include <cuda_runtime.h>
#include <math.h>

// TemplatePointwiseAttention fused kernel, fp32, warp-per-4-pairs,
// pair-packed f32x2 math (fma.rn.f32x2 = FFMA2, 2x fp32 throughput).
// Shapes: B=1, T=4, L=384, c_z=128, c_t=64, H=4, C=16.
//
// Activations stored pair-interleaved in smem: 2 groups g of 2 pairs each.
// Every weight load feeds 4 pairs; every packed FMA computes 2 pairs.

namespace {
constexpr int L_ = 384;
constexpr int NPAIR = L_ * L_;        // 147456
constexpr int NP = 4;                 // pairs per warp iteration (2 groups x 2)
constexpr int NB = NPAIR / NP;        // 36864
constexpr int WARPS = 4;
constexpr int NTHREADS = WARPS * 32;  // 128
constexpr int GRID = 152 * 4;         // 608

// per-warp scratch (floats), pair-packed {k0,k1} innermost:
constexpr int R_OFF = 0;      // r2/u2 [g][h][m][2]   : 1024
constexpr int T_OFF = 1024;   // tn2  [g][t][m][2]    : 1024 (zn2 [g][128][2] overlays)
constexpr int Q_OFF = 2048;   // q2   [g][n][2]       : 256
constexpr int A_OFF = 2304;   // at2  [g][16][2]      : 64
constexpr int O_OFF = 2368;   // o2   [g][n][2]       : 256
constexpr int SCR_W = 2624;
constexpr int SMEM_FLOATS = WARPS * SCR_W;   // 10496 -> 41984 B (static)

__device__ float g_WkT[64 * 64];   // WkT[c][m] = Wk[m][c]

using u64 = unsigned long long;
__device__ __forceinline__ u64 pk2(float x, float y) {
    u64 r; asm("mov.b64 %0,{%1,%2};" : "=l"(r) : "f"(x), "f"(y)); return r;
}
__device__ __forceinline__ void up2(u64 v, float& x, float& y) {
    asm("mov.b64 {%0,%1},%2;" : "=f"(x), "=f"(y) : "l"(v));
}
__device__ __forceinline__ void fma2(u64& d, u64 a, u64 b) {
    asm("fma.rn.f32x2 %0,%1,%2,%0;" : "+l"(d) : "l"(a), "l"(b));
}
__device__ __forceinline__ u64 add2(u64 a, u64 b) {
    u64 r; asm("add.rn.f32x2 %0,%1,%2;" : "=l"(r) : "l"(a), "l"(b)); return r;
}
__device__ __forceinline__ float4 ldcs4(const float* p) { return __ldcs((const float4*)p); }
__device__ __forceinline__ float2 ldcs2(const float* p) { return __ldcs((const float2*)p); }
} // namespace

__global__ void tpa_prep(const float* __restrict__ Wk) {
    int idx = blockIdx.x * blockDim.x + threadIdx.x;
    if (idx < 4096) {
        int m = idx >> 6, c = idx & 63;
        g_WkT[c * 64 + m] = Wk[idx];
    }
}

__global__ __launch_bounds__(NTHREADS, 4) void tpa_fused(
    const float* __restrict__ tin,   // [4,384,384,64]
    const float* __restrict__ zin,   // [384,384,128]
    const float* __restrict__ mask,  // [4,384]
    const float* __restrict__ zg_, const float* __restrict__ zb_,
    const float* __restrict__ tg_, const float* __restrict__ tb_,
    const float* __restrict__ Wq,    // [128,64]
    const float* __restrict__ Wv,    // [64,64]
    const float* __restrict__ Wo,    // [64,128]
    const float* __restrict__ bo,    // [128]
    float* __restrict__ out)         // [384,384,128]
{
    __shared__ float sm[SMEM_FLOATS];
    const int tid  = threadIdx.x;
    const int warp = tid >> 5, lane = tid & 31;
    float* scr = sm + warp * SCR_W;

    const float4 zg = *(const float4*)(zg_ + lane * 4);
    const float4 zb = *(const float4*)(zb_ + lane * 4);
    const float2 tg = *(const float2*)(tg_ + lane * 2);
    const float2 tb = *(const float2*)(tb_ + lane * 2);
    const float4 bo4 = *(const float4*)(bo + lane * 4);

    const int idx16 = lane & 15;
    const int half  = lane >> 4;     // m-half for logit partial
    const int t_of  = idx16 >> 2;    // template idx (logits lane)
    const int h_of  = idx16 & 3;     // head idx (logits lane)
    const int h_o   = lane >> 3;     // head owned in o-stage (n = 2*lane)

    const int gw = blockIdx.x * WARPS + warp;
    const int nw = GRID * WARPS;

    for (int b = gw; b < NB; b += nw) {
        const int p0 = b * NP;
        const int i  = p0 / L_;          // all 4 pairs share row i
        const int j0 = p0 - i * L_;

        // ---- z loads + LN; store zn pair-packed ----
        #pragma unroll
        for (int g = 0; g < 2; g++) {
            float4 zn[2];
            #pragma unroll
            for (int kk = 0; kk < 2; kk++) {
                float4 zv = ldcs4(zin + (size_t)(p0 + 2 * g + kk) * 128 + lane * 4);
                float s  = zv.x + zv.y + zv.z + zv.w;
                float ss = zv.x * zv.x + zv.y * zv.y + zv.z * zv.z + zv.w * zv.w;
                #pragma unroll
                for (int o = 16; o > 0; o >>= 1) {
                    s  += __shfl_xor_sync(0xffffffffu, s,  o);
                    ss += __shfl_xor_sync(0xffffffffu, ss, o);
                }
                float mu   = s * (1.0f / 128.0f);
                float rstd = rsqrtf(fmaf(ss, 1.0f / 128.0f, -mu * mu) + 1e-5f);
                zn[kk].x = (zv.x - mu) * rstd * zg.x + zb.x;
                zn[kk].y = (zv.y - mu) * rstd * zg.y + zb.y;
                zn[kk].z = (zv.z - mu) * rstd * zg.z + zb.z;
                zn[kk].w = (zv.w - mu) * rstd * zg.w + zb.w;
            }
            // zn2[g][m]{k0,k1} at T_OFF + (g*128+m)*2 ; lane owns m=4l..4l+3
            float* zp = scr + T_OFF + (g * 128 + 4 * lane) * 2;
            *(float4*)(zp)     = make_float4(zn[0].x, zn[1].x, zn[0].y, zn[1].y);
            *(float4*)(zp + 4) = make_float4(zn[0].z, zn[1].z, zn[0].w, zn[1].w);
        }
        __syncwarp();

        // ---- prefetch t (streaming) ----
        float2 tv[NP][4];
        #pragma unroll
        for (int k = 0; k < NP; k++)
            #pragma unroll
            for (int t = 0; t < 4; t++)
                tv[k][t] = ldcs2(tin + ((size_t)(t * L_ + i) * L_ + (j0 + k)) * 64 + lane * 2);

        // ---- q[n] = zn . Wq[:,n]; lane owns n = 2l, 2l+1; packed over pairs ----
        {
            u64 acc[2][2] = {{0, 0}, {0, 0}};   // [g][n-slot]
            const float* wq = Wq + 2 * lane;
            #pragma unroll 8
            for (int m = 0; m < 128; m += 2) {
                float2 w0 = *(const float2*)(wq + m * 64);
                float2 w1 = *(const float2*)(wq + (m + 1) * 64);
                u64 s00 = pk2(w0.x, w0.x), s01 = pk2(w0.y, w0.y);
                u64 s10 = pk2(w1.x, w1.x), s11 = pk2(w1.y, w1.y);
                #pragma unroll
                for (int g = 0; g < 2; g++) {
                    ulonglong2 z4 = *(const ulonglong2*)(scr + T_OFF + (g * 128 + m) * 2);
                    fma2(acc[g][0], z4.x, s00); fma2(acc[g][1], z4.x, s01);
                    fma2(acc[g][0], z4.y, s10); fma2(acc[g][1], z4.y, s11);
                }
            }
            #pragma unroll
            for (int g = 0; g < 2; g++) {
                ulonglong2 st; st.x = acc[g][0]; st.y = acc[g][1];
                *(ulonglong2*)(scr + Q_OFF + (g * 64 + 2 * lane) * 2) = st;
            }
        }
        __syncwarp();

        // ---- r[h][m] = sum_c q[h*16+c]*WkT[h*16+c][m]; lane owns m=2l,2l+1 ----
        #pragma unroll
        for (int h = 0; h < 4; h++) {
            u64 acc[2][2] = {{0, 0}, {0, 0}};
            #pragma unroll
            for (int c = 0; c < 16; c += 2) {
                const float* wk = g_WkT + (h * 16 + c) * 64 + 2 * lane;
                float2 w0 = *(const float2*)(wk);
                float2 w1 = *(const float2*)(wk + 64);
                u64 s00 = pk2(w0.x, w0.x), s01 = pk2(w0.y, w0.y);
                u64 s10 = pk2(w1.x, w1.x), s11 = pk2(w1.y, w1.y);
                #pragma unroll
                for (int g = 0; g < 2; g++) {
                    ulonglong2 q4 = *(const ulonglong2*)(scr + Q_OFF + (g * 64 + h * 16 + c) * 2);
                    fma2(acc[g][0], q4.x, s00); fma2(acc[g][1], q4.x, s01);
                    fma2(acc[g][0], q4.y, s10); fma2(acc[g][1], q4.y, s11);
                }
            }
            #pragma unroll
            for (int g = 0; g < 2; g++) {
                ulonglong2 st; st.x = acc[g][0]; st.y = acc[g][1];
                *(ulonglong2*)(scr + R_OFF + ((g * 4 + h) * 64 + 2 * lane) * 2) = st;
            }
        }
        __syncwarp();   // q reads done; zn region may be overwritten by tn below

        // ---- t layernorms; store tn pair-packed (lane owns m = 2l, 2l+1) ----
        #pragma unroll
        for (int k = 0; k < NP; k++)
            #pragma unroll
            for (int t = 0; t < 4; t++) {
                float2 v = tv[k][t];
                float s  = v.x + v.y;
                float ss = v.x * v.x + v.y * v.y;
                #pragma unroll
                for (int o = 16; o > 0; o >>= 1) {
                    s  += __shfl_xor_sync(0xffffffffu, s,  o);
                    ss += __shfl_xor_sync(0xffffffffu, ss, o);
                }
                float mu   = s * (1.0f / 64.0f);
                float rstd = rsqrtf(fmaf(ss, 1.0f / 64.0f, -mu * mu) + 1e-5f);
                tv[k][t].x = (v.x - mu) * rstd * tg.x + tb.x;
                tv[k][t].y = (v.y - mu) * rstd * tg.y + tb.y;
            }
        #pragma unroll
        for (int g = 0; g < 2; g++)
            #pragma unroll
            for (int t = 0; t < 4; t++) {
                float2 a = tv[2 * g][t], bv = tv[2 * g + 1][t];
                *(float4*)(scr + T_OFF + ((g * 4 + t) * 64 + 2 * lane) * 2) =
                    make_float4(a.x, bv.x, a.y, bv.y);
            }
        __syncwarp();

        // ---- logits (packed dot) + masked softmax over t ----
        const float pm_i = mask[t_of * L_ + i];
        #pragma unroll
        for (int g = 0; g < 2; g++) {
            const float* tnp = scr + T_OFF + ((g * 4 + t_of) * 64 + half * 32) * 2;
            const float* rp  = scr + R_OFF + ((g * 4 + h_of) * 64 + half * 32) * 2;
            u64 acc = 0;
            #pragma unroll
            for (int s4 = 0; s4 < 32; s4 += 2) {
                ulonglong2 a = *(const ulonglong2*)(tnp + s4 * 2);
                ulonglong2 c = *(const ulonglong2*)(rp  + s4 * 2);
                fma2(acc, a.x, c.x); fma2(acc, a.y, c.y);
            }
            acc = add2(acc, (u64)__shfl_xor_sync(0xffffffffu, acc, 16));
            float l0, l1; up2(acc, l0, l1);
            float at[2];
            #pragma unroll
            for (int kk = 0; kk < 2; kk++) {
                float logit = (kk == 0 ? l0 : l1) * 0.25f;
                float pm = pm_i * mask[t_of * L_ + j0 + 2 * g + kk];
                logit = (pm == 0.0f) ? -1e9f : logit;
                float mx = fmaxf(logit, __shfl_xor_sync(0xffffffffu, logit, 4));
                mx = fmaxf(mx, __shfl_xor_sync(0xffffffffu, mx, 8));
                float e = __expf(logit - mx);
                float den = e + __shfl_xor_sync(0xffffffffu, e, 4);
                den += __shfl_xor_sync(0xffffffffu, den, 8);
                float attn = __fdividef(e, den) * pm;
                float s2 = attn + __shfl_xor_sync(0xffffffffu, attn, 4);
                s2 += __shfl_xor_sync(0xffffffffu, s2, 8);
                at[kk] = __fdividef(attn, fmaxf(s2, 1e-8f));
            }
            *(float2*)(scr + A_OFF + (g * 16 + t_of * 4 + h_of) * 2) =
                make_float2(at[0], at[1]);   // l and l^16 write same value
        }
        __syncwarp();

        // ---- u[h][m] = sum_t attn[t,h]*tn[t][m] (packed); lane owns m=2l,2l+1 ----
        #pragma unroll
        for (int g = 0; g < 2; g++) {
            u64 acc[4][2] = {{0,0},{0,0},{0,0},{0,0}};   // [h][m-slot]
            #pragma unroll
            for (int t = 0; t < 4; t++) {
                ulonglong2 a01 = *(const ulonglong2*)(scr + A_OFF + (g * 16 + t * 4) * 2);
                ulonglong2 a23 = *(const ulonglong2*)(scr + A_OFF + (g * 16 + t * 4 + 2) * 2);
                ulonglong2 t4  = *(const ulonglong2*)(scr + T_OFF + ((g * 4 + t) * 64 + 2 * lane) * 2);
                fma2(acc[0][0], a01.x, t4.x); fma2(acc[0][1], a01.x, t4.y);
                fma2(acc[1][0], a01.y, t4.x); fma2(acc[1][1], a01.y, t4.y);
                fma2(acc[2][0], a23.x, t4.x); fma2(acc[2][1], a23.x, t4.y);
                fma2(acc[3][0], a23.y, t4.x); fma2(acc[3][1], a23.y, t4.y);
            }
            #pragma unroll
            for (int h = 0; h < 4; h++) {
                ulonglong2 st; st.x = acc[h][0]; st.y = acc[h][1];
                *(ulonglong2*)(scr + R_OFF + ((g * 4 + h) * 64 + 2 * lane) * 2) = st;
            }
        }
        __syncwarp();

        // ---- o[n] = u[h(n)] . Wv[:,n]; lane owns n = 2l, 2l+1 ----
        {
            u64 acc[2][2] = {{0, 0}, {0, 0}};
            const float* wv = Wv + 2 * lane;
            #pragma unroll 8
            for (int m = 0; m < 64; m += 2) {
                float2 w0 = *(const float2*)(wv + m * 64);
                float2 w1 = *(const float2*)(wv + (m + 1) * 64);
                u64 s00 = pk2(w0.x, w0.x), s01 = pk2(w0.y, w0.y);
                u64 s10 = pk2(w1.x, w1.x), s11 = pk2(w1.y, w1.y);
                #pragma unroll
                for (int g = 0; g < 2; g++) {
                    ulonglong2 u4 = *(const ulonglong2*)(scr + R_OFF + ((g * 4 + h_o) * 64 + m) * 2);
                    fma2(acc[g][0], u4.x, s00); fma2(acc[g][1], u4.x, s01);
                    fma2(acc[g][0], u4.y, s10); fma2(acc[g][1], u4.y, s11);
                }
            }
            #pragma unroll
            for (int g = 0; g < 2; g++) {
                ulonglong2 st; st.x = acc[g][0]; st.y = acc[g][1];
                *(ulonglong2*)(scr + O_OFF + (g * 64 + 2 * lane) * 2) = st;
            }
        }
        __syncwarp();

        // ---- res[j'] = o . Wo[:,j'] + bo; lane owns j' = 4l..4l+3 ----
        {
            u64 acc[2][4];
            #pragma unroll
            for (int g = 0; g < 2; g++) {
                acc[g][0] = pk2(bo4.x, bo4.x); acc[g][1] = pk2(bo4.y, bo4.y);
                acc[g][2] = pk2(bo4.z, bo4.z); acc[g][3] = pk2(bo4.w, bo4.w);
            }
            const float* wo = Wo + 4 * lane;
            #pragma unroll 8
            for (int n = 0; n < 64; n += 2) {
                float4 w0 = *(const float4*)(wo + n * 128);
                float4 w1 = *(const float4*)(wo + (n + 1) * 128);
                u64 a0 = pk2(w0.x, w0.x), a1 = pk2(w0.y, w0.y);
                u64 a2 = pk2(w0.z, w0.z), a3 = pk2(w0.w, w0.w);
                u64 b0 = pk2(w1.x, w1.x), b1 = pk2(w1.y, w1.y);
                u64 b2 = pk2(w1.z, w1.z), b3 = pk2(w1.w, w1.w);
                #pragma unroll
                for (int g = 0; g < 2; g++) {
                    ulonglong2 o4 = *(const ulonglong2*)(scr + O_OFF + (g * 64 + n) * 2);
                    fma2(acc[g][0], o4.x, a0); fma2(acc[g][1], o4.x, a1);
                    fma2(acc[g][2], o4.x, a2); fma2(acc[g][3], o4.x, a3);
                    fma2(acc[g][0], o4.y, b0); fma2(acc[g][1], o4.y, b1);
                    fma2(acc[g][2], o4.y, b2); fma2(acc[g][3], o4.y, b3);
                }
            }
            #pragma unroll
            for (int g = 0; g < 2; g++) {
                float4 r0, r1;
                up2(acc[g][0], r0.x, r1.x); up2(acc[g][1], r0.y, r1.y);
                up2(acc[g][2], r0.z, r1.z); up2(acc[g][3], r0.w, r1.w);
                __stcs((float4*)(out + (size_t)(p0 + 2 * g)     * 128 + 4 * lane), r0);
                __stcs((float4*)(out + (size_t)(p0 + 2 * g + 1) * 128 + 4 * lane), r1);
            }
        }
        __syncwarp();   // scratch reuse barrier before next block
    }
}

extern "C" void kernel_launch(void* const* d_in, const int* in_sizes, int n_in,
                              void* d_out, int out_size) {
    (void)in_sizes; (void)n_in; (void)out_size;
    tpa_prep<<<16, 256>>>((const float*)d_in[8]);   // Wk
    tpa_fused<<<GRID, NTHREADS>>>(
        (const float*)d_in[0],  // t
        (const float*)d_in[1],  // z
        (const float*)d_in[2],  // template_mask
        (const float*)d_in[3],  // z_ln_g
        (const float*)d_in[4],  // z_ln_b
        (const float*)d_in[5],  // t_ln_g
        (const float*)d_in[6],  // t_ln_b
        (const float*)d_in[7],  // Wq
        (const float*)d_in[9],  // Wv
        (const float*)d_in[10], // Wo
        (const float*)d_in[11], // bo
        (float*)d_out);
}

// round 6
// speedup vs baseline: 1.0364x; 1.0364x over previous
#include <cuda_runtime.h>
#include <math.h>

// TemplatePointwiseAttention fused kernel, fp32, warp-per-8-pairs.
// Shapes: B=1, T=4, L=384, c_z=128, c_t=64, H=4, C=16.
//
// R3 dataflow (305us) with NP=4 -> NP=8: every weight LDG now feeds 8 pairs,
// halving the dominant L1 weight traffic (R3 ncu: L1 82%, weights ~24KB/pair).
// 2 warps/block, 44KB static smem, grid 608 (4 blocks/SM, 8 warps/SM).

namespace {
constexpr int L_ = 384;
constexpr int NPAIR = L_ * L_;        // 147456
constexpr int NP = 8;                 // pairs per warp iteration
constexpr int NB = NPAIR / NP;        // 18432
constexpr int WARPS = 2;
constexpr int NTHREADS = WARPS * 32;  // 64
constexpr int GRID = 152 * 4;         // 608

// per-pair scratch (floats):
//   [0..271]   r_s  (4 x 68)  -> reused as u after softmax
//   [272..543] tn_s (4 x 68)  -> first 128 floats overlay zn
//   [544..607] q_s  (64)
//   [608..623] at_s (16)
//   [624..687] o_s  (64)
constexpr int SCR_P = 688;
constexpr int SCR_W = NP * SCR_P;                    // 5504 per warp
constexpr int SMEM_FLOATS = WARPS * SCR_W;           // 11008 -> 44032 B

__device__ float g_WkT[64 * 64];   // WkT[c][m] = Wk[m][c]

__device__ __forceinline__ float dot4(float4 a, float4 b) {
    return fmaf(a.x, b.x, fmaf(a.y, b.y, fmaf(a.z, b.z, a.w * b.w)));
}
__device__ __forceinline__ float4 ldcs4(const float* p) { return __ldcs((const float4*)p); }
__device__ __forceinline__ float2 ldcs2(const float* p) { return __ldcs((const float2*)p); }
} // namespace

__global__ void tpa_prep(const float* __restrict__ Wk) {
    int idx = blockIdx.x * blockDim.x + threadIdx.x;
    if (idx < 4096) {
        int m = idx >> 6, c = idx & 63;
        g_WkT[c * 64 + m] = Wk[idx];
    }
}

__global__ __launch_bounds__(NTHREADS, 4) void tpa_fused(
    const float* __restrict__ tin,   // [4,384,384,64]
    const float* __restrict__ zin,   // [384,384,128]
    const float* __restrict__ mask,  // [4,384]
    const float* __restrict__ zg_, const float* __restrict__ zb_,
    const float* __restrict__ tg_, const float* __restrict__ tb_,
    const float* __restrict__ Wq,    // [128,64]
    const float* __restrict__ Wv,    // [64,64]
    const float* __restrict__ Wo,    // [64,128]
    const float* __restrict__ bo,    // [128]
    float* __restrict__ out)         // [384,384,128]
{
    __shared__ float sm[SMEM_FLOATS];
    const int tid  = threadIdx.x;
    const int warp = tid >> 5, lane = tid & 31;
    float* scr = sm + warp * SCR_W;

    const float4 zg = *(const float4*)(zg_ + lane * 4);
    const float4 zb = *(const float4*)(zb_ + lane * 4);
    const float2 tg = *(const float2*)(tg_ + lane * 2);
    const float2 tb = *(const float2*)(tb_ + lane * 2);
    const float4 bo4 = *(const float4*)(bo + lane * 4);

    const int idx16 = lane & 15;
    const int half  = lane >> 4;     // m-half for logit partial
    const int t_of  = idx16 >> 2;    // template idx (logits lane)
    const int h_of  = idx16 & 3;     // head idx (logits lane)
    const int h_o   = lane >> 3;     // head owned in o-stage (n = 2*lane)

    const int gw = blockIdx.x * WARPS + warp;
    const int nw = GRID * WARPS;

    for (int b = gw; b < NB; b += nw) {
        const int p0 = b * NP;
        const int i  = p0 / L_;          // all 8 pairs share row i (8 | 384)
        const int j0 = p0 - i * L_;

        // ---- z loads + LN (8 pairs); zn overlays tn region ----
        #pragma unroll
        for (int k = 0; k < NP; k++) {
            float4 zv = ldcs4(zin + (size_t)(p0 + k) * 128 + lane * 4);
            float s  = zv.x + zv.y + zv.z + zv.w;
            float ss = zv.x * zv.x + zv.y * zv.y + zv.z * zv.z + zv.w * zv.w;
            #pragma unroll
            for (int o = 16; o > 0; o >>= 1) {
                s  += __shfl_xor_sync(0xffffffffu, s,  o);
                ss += __shfl_xor_sync(0xffffffffu, ss, o);
            }
            float mu   = s * (1.0f / 128.0f);
            float rstd = rsqrtf(fmaf(ss, 1.0f / 128.0f, -mu * mu) + 1e-5f);
            float4 znv;
            znv.x = (zv.x - mu) * rstd * zg.x + zb.x;
            znv.y = (zv.y - mu) * rstd * zg.y + zb.y;
            znv.z = (zv.z - mu) * rstd * zg.z + zb.z;
            znv.w = (zv.w - mu) * rstd * zg.w + zb.w;
            *(float4*)(scr + k * SCR_P + 272 + lane * 4) = znv;
        }
        __syncwarp();

        // ---- prefetch t batch0 (pairs 0..3, streaming; consumed after q/r) ----
        float2 tv[4][4];
        #pragma unroll
        for (int k = 0; k < 4; k++)
            #pragma unroll
            for (int t = 0; t < 4; t++)
                tv[k][t] = ldcs2(tin + ((size_t)(t * L_ + i) * L_ + (j0 + k)) * 64 + lane * 2);

        // ---- q[n] = zn . Wq[:,n]; lane owns n = 2l, 2l+1; 8-pair amortized ----
        {
            float2 qacc[NP];
            #pragma unroll
            for (int k = 0; k < NP; k++) qacc[k] = make_float2(0.f, 0.f);
            const float* wq = Wq + 2 * lane;
            #pragma unroll 4
            for (int m = 0; m < 128; m += 2) {
                float2 w0 = *(const float2*)(wq + m * 64);
                float2 w1 = *(const float2*)(wq + (m + 1) * 64);
                #pragma unroll
                for (int k = 0; k < NP; k++) {
                    float2 zz = *(const float2*)(scr + k * SCR_P + 272 + m);  // bcast
                    qacc[k].x = fmaf(zz.x, w0.x, fmaf(zz.y, w1.x, qacc[k].x));
                    qacc[k].y = fmaf(zz.x, w0.y, fmaf(zz.y, w1.y, qacc[k].y));
                }
            }
            #pragma unroll
            for (int k = 0; k < NP; k++)
                *(float2*)(scr + k * SCR_P + 544 + 2 * lane) = qacc[k];
        }
        __syncwarp();

        // ---- r[h][m] = sum_c q[h*16+c]*WkT[h*16+c][m]; lane owns m=2l,2l+1 ----
        #pragma unroll
        for (int h = 0; h < 4; h++) {
            float2 racc[NP];
            #pragma unroll
            for (int k = 0; k < NP; k++) racc[k] = make_float2(0.f, 0.f);
            #pragma unroll
            for (int c = 0; c < 16; c += 4) {
                const float* wk = g_WkT + (h * 16 + c) * 64 + 2 * lane;
                float2 w0 = *(const float2*)(wk);
                float2 w1 = *(const float2*)(wk + 64);
                float2 w2 = *(const float2*)(wk + 128);
                float2 w3 = *(const float2*)(wk + 192);
                #pragma unroll
                for (int k = 0; k < NP; k++) {
                    float4 qv = *(const float4*)(scr + k * SCR_P + 544 + h * 16 + c);
                    racc[k].x = fmaf(qv.x, w0.x, fmaf(qv.y, w1.x,
                                fmaf(qv.z, w2.x, fmaf(qv.w, w3.x, racc[k].x))));
                    racc[k].y = fmaf(qv.x, w0.y, fmaf(qv.y, w1.y,
                                fmaf(qv.z, w2.y, fmaf(qv.w, w3.y, racc[k].y))));
                }
            }
            #pragma unroll
            for (int k = 0; k < NP; k++)
                *(float2*)(scr + k * SCR_P + h * 68 + 2 * lane) = racc[k];
        }
        __syncwarp();   // q/zn reads done; tn may overwrite zn region

        // ---- t layernorms, batch0 then batch1 (lane owns m = 2l, 2l+1) ----
        #pragma unroll
        for (int g = 0; g < 2; g++) {
            if (g == 1) {   // load batch1 (pairs 4..7)
                #pragma unroll
                for (int k = 0; k < 4; k++)
                    #pragma unroll
                    for (int t = 0; t < 4; t++)
                        tv[k][t] = ldcs2(tin + ((size_t)(t * L_ + i) * L_ + (j0 + 4 + k)) * 64 + lane * 2);
            }
            #pragma unroll
            for (int k = 0; k < 4; k++)
                #pragma unroll
                for (int t = 0; t < 4; t++) {
                    float2 v = tv[k][t];
                    float s  = v.x + v.y;
                    float ss = v.x * v.x + v.y * v.y;
                    #pragma unroll
                    for (int o = 16; o > 0; o >>= 1) {
                        s  += __shfl_xor_sync(0xffffffffu, s,  o);
                        ss += __shfl_xor_sync(0xffffffffu, ss, o);
                    }
                    float mu   = s * (1.0f / 64.0f);
                    float rstd = rsqrtf(fmaf(ss, 1.0f / 64.0f, -mu * mu) + 1e-5f);
                    float2 tnv;
                    tnv.x = (v.x - mu) * rstd * tg.x + tb.x;
                    tnv.y = (v.y - mu) * rstd * tg.y + tb.y;
                    *(float2*)(scr + (g * 4 + k) * SCR_P + 272 + t * 68 + lane * 2) = tnv;
                }
        }
        __syncwarp();

        // ---- logits + masked softmax over t (per pair) ----
        const float pm_i = mask[t_of * L_ + i];
        #pragma unroll
        for (int k = 0; k < NP; k++) {
            const float* tnp = scr + k * SCR_P + 272 + t_of * 68 + half * 32;
            const float* rp  = scr + k * SCR_P + h_of * 68 + half * 32;
            float acc = 0.f;
            #pragma unroll
            for (int s4 = 0; s4 < 32; s4 += 4)
                acc += dot4(*(const float4*)(tnp + s4), *(const float4*)(rp + s4));
            acc += __shfl_xor_sync(0xffffffffu, acc, 16);
            float logit = acc * 0.25f;

            float pm = pm_i * mask[t_of * L_ + j0 + k];
            logit = (pm == 0.0f) ? -1e9f : logit;

            float mx = fmaxf(logit, __shfl_xor_sync(0xffffffffu, logit, 4));
            mx = fmaxf(mx, __shfl_xor_sync(0xffffffffu, mx, 8));
            float e = __expf(logit - mx);
            float den = e + __shfl_xor_sync(0xffffffffu, e, 4);
            den += __shfl_xor_sync(0xffffffffu, den, 8);
            float attn = __fdividef(e, den) * pm;
            float s2 = attn + __shfl_xor_sync(0xffffffffu, attn, 4);
            s2 += __shfl_xor_sync(0xffffffffu, s2, 8);
            attn = __fdividef(attn, fmaxf(s2, 1e-8f));
            scr[k * SCR_P + 608 + t_of * 4 + h_of] = attn;  // l and l^16 same val
        }
        __syncwarp();

        // ---- u[h][m] = sum_t attn[t,h]*tn[t][m]; lane owns m=lane,lane+32 ----
        #pragma unroll
        for (int k = 0; k < NP; k++) {
            float* pk = scr + k * SCR_P;
            float u0[4] = {0.f, 0.f, 0.f, 0.f};
            float u1[4] = {0.f, 0.f, 0.f, 0.f};
            #pragma unroll
            for (int t = 0; t < 4; t++) {
                float  a0 = pk[272 + t * 68 + lane];
                float  a1 = pk[272 + t * 68 + lane + 32];
                float4 av = *(const float4*)(pk + 608 + t * 4);   // attn[t][0..3]
                u0[0] = fmaf(av.x, a0, u0[0]); u1[0] = fmaf(av.x, a1, u1[0]);
                u0[1] = fmaf(av.y, a0, u0[1]); u1[1] = fmaf(av.y, a1, u1[1]);
                u0[2] = fmaf(av.z, a0, u0[2]); u1[2] = fmaf(av.z, a1, u1[2]);
                u0[3] = fmaf(av.w, a0, u0[3]); u1[3] = fmaf(av.w, a1, u1[3]);
            }
            #pragma unroll
            for (int h = 0; h < 4; h++) {
                pk[h * 68 + lane]      = u0[h];   // overwrite r with u
                pk[h * 68 + lane + 32] = u1[h];
            }
        }
        __syncwarp();

        // ---- o[n] = u[h(n)] . Wv[:,n]; lane owns n = 2l, 2l+1 ----
        {
            float2 oacc[NP];
            #pragma unroll
            for (int k = 0; k < NP; k++) oacc[k] = make_float2(0.f, 0.f);
            const float* wv = Wv + 2 * lane;
            #pragma unroll 4
            for (int m = 0; m < 64; m += 2) {
                float2 w0 = *(const float2*)(wv + m * 64);
                float2 w1 = *(const float2*)(wv + (m + 1) * 64);
                #pragma unroll
                for (int k = 0; k < NP; k++) {
                    float2 uu = *(const float2*)(scr + k * SCR_P + h_o * 68 + m);
                    oacc[k].x = fmaf(uu.x, w0.x, fmaf(uu.y, w1.x, oacc[k].x));
                    oacc[k].y = fmaf(uu.x, w0.y, fmaf(uu.y, w1.y, oacc[k].y));
                }
            }
            #pragma unroll
            for (int k = 0; k < NP; k++)
                *(float2*)(scr + k * SCR_P + 624 + 2 * lane) = oacc[k];
        }
        __syncwarp();

        // ---- res[j'] = o . Wo[:,j'] + bo; lane owns j' = 4l..4l+3 ----
        {
            float4 acc[NP];
            #pragma unroll
            for (int k = 0; k < NP; k++) acc[k] = bo4;
            const float* wo = Wo + 4 * lane;
            #pragma unroll 4
            for (int n = 0; n < 64; n += 2) {
                float4 w0 = *(const float4*)(wo + n * 128);
                float4 w1 = *(const float4*)(wo + (n + 1) * 128);
                #pragma unroll
                for (int k = 0; k < NP; k++) {
                    float2 oo = *(const float2*)(scr + k * SCR_P + 624 + n);  // bcast
                    acc[k].x = fmaf(oo.x, w0.x, fmaf(oo.y, w1.x, acc[k].x));
                    acc[k].y = fmaf(oo.x, w0.y, fmaf(oo.y, w1.y, acc[k].y));
                    acc[k].z = fmaf(oo.x, w0.z, fmaf(oo.y, w1.z, acc[k].z));
                    acc[k].w = fmaf(oo.x, w0.w, fmaf(oo.y, w1.w, acc[k].w));
                }
            }
            #pragma unroll
            for (int k = 0; k < NP; k++)
                __stcs((float4*)(out + (size_t)(p0 + k) * 128 + 4 * lane), acc[k]);
        }
        __syncwarp();   // scratch reuse barrier before next block
    }
}

extern "C" void kernel_launch(void* const* d_in, const int* in_sizes, int n_in,
                              void* d_out, int out_size) {
    (void)in_sizes; (void)n_in; (void)out_size;
    tpa_prep<<<16, 256>>>((const float*)d_in[8]);   // Wk
    tpa_fused<<<GRID, NTHREADS>>>(
        (const float*)d_in[0],  // t
        (const float*)d_in[1],  // z
        (const float*)d_in[2],  // template_mask
        (const float*)d_in[3],  // z_ln_g
        (const float*)d_in[4],  // z_ln_b
        (const float*)d_in[5],  // t_ln_g
        (const float*)d_in[6],  // t_ln_b
        (const float*)d_in[7],  // Wq
        (const float*)d_in[9],  // Wv
        (const float*)d_in[10], // Wo
        (const float*)d_in[11], // bo
        (float*)d_out);
}